// round 2
// baseline (speedup 1.0000x reference)
#include <cuda_runtime.h>
#include <cuda_bf16.h>

// Inputs (metadata order):
//   d_in[0]: pre     float32  [N, 3]   (log-softmax)
//   d_in[1]: y_true  int32    [N]      (jax coerces int64 -> int32 w/o x64)
//   d_in[2]: weight  float32  scalar
// Output: float32 scalar = -sum(w_i * pre[i, y_i]) / N,
//   w_i = weight if |argmax(pre_i) - y_i| == 2 else 1.

#define NBLOCKS 2048
#define NTHREADS 256

__device__ float g_partials[NBLOCKS];

__device__ __forceinline__ float row_term(float a, float b, float c, int yt, float w) {
    // argmax with first-occurrence tie-breaking (strict >)
    int pred = 0;
    float best = a;
    if (b > best) { best = b; pred = 1; }
    if (c > best) { pred = 2; }
    float picked = (yt == 0) ? a : ((yt == 1) ? b : c);
    int d = pred - yt;
    bool penal = (d == 2) || (d == -2);
    return penal ? (w * picked) : picked;
}

__global__ void __launch_bounds__(NTHREADS)
nll_partial_kernel(const float* __restrict__ pre,
                   const int* __restrict__ y,
                   const float* __restrict__ wp,
                   int n) {
    const float4* p4 = reinterpret_cast<const float4*>(pre);
    const int4*   y4 = reinterpret_cast<const int4*>(y);
    const float w = *wp;

    const int nquad  = n >> 2;               // rows processed 4 at a time
    const int stride = gridDim.x * blockDim.x;

    float acc = 0.0f;

    for (int q = blockIdx.x * blockDim.x + threadIdx.x; q < nquad; q += stride) {
        // 4 rows = 12 floats = 3 float4, 4 int32 = 1 int4 (all 16B aligned)
        float4 f0 = p4[3 * q + 0];
        float4 f1 = p4[3 * q + 1];
        float4 f2 = p4[3 * q + 2];
        int4   yv = y4[q];

        acc += row_term(f0.x, f0.y, f0.z, yv.x, w);
        acc += row_term(f0.w, f1.x, f1.y, yv.y, w);
        acc += row_term(f1.z, f1.w, f2.x, yv.z, w);
        acc += row_term(f2.y, f2.z, f2.w, yv.w, w);
    }

    // scalar tail (N divisible by 4 here, but stay correct)
    for (int i = (nquad << 2) + blockIdx.x * blockDim.x + threadIdx.x; i < n; i += stride) {
        float a = pre[3 * i + 0];
        float b = pre[3 * i + 1];
        float c = pre[3 * i + 2];
        acc += row_term(a, b, c, y[i], w);
    }

    // warp reduce
    #pragma unroll
    for (int off = 16; off > 0; off >>= 1)
        acc += __shfl_down_sync(0xFFFFFFFFu, acc, off);

    __shared__ float s[NTHREADS / 32];
    int lane = threadIdx.x & 31;
    int wid  = threadIdx.x >> 5;
    if (lane == 0) s[wid] = acc;
    __syncthreads();

    if (wid == 0) {
        float v = (lane < NTHREADS / 32) ? s[lane] : 0.0f;
        #pragma unroll
        for (int off = 16; off > 0; off >>= 1)
            v += __shfl_down_sync(0xFFFFFFFFu, v, off);
        if (lane == 0) g_partials[blockIdx.x] = v;
    }
}

__global__ void __launch_bounds__(1024)
nll_finish_kernel(float* __restrict__ out, float inv_n_neg) {
    __shared__ float s[1024];
    int t = threadIdx.x;
    s[t] = g_partials[t] + g_partials[t + 1024];
    __syncthreads();
    #pragma unroll
    for (int off = 512; off >= 1; off >>= 1) {
        if (t < off) s[t] += s[t + off];
        __syncthreads();
    }
    if (t == 0) out[0] = s[0] * inv_n_neg;   // = -sum / N
}

extern "C" void kernel_launch(void* const* d_in, const int* in_sizes, int n_in,
                              void* d_out, int out_size) {
    const float* pre = (const float*)d_in[0];
    const int*   y   = (const int*)d_in[1];
    const float* wp  = (const float*)d_in[2];
    float* out = (float*)d_out;

    const int n = in_sizes[1];   // y_true element count = number of rows

    nll_partial_kernel<<<NBLOCKS, NTHREADS>>>(pre, y, wp, n);
    nll_finish_kernel<<<1, 1024>>>(out, -1.0f / (float)n);
}